// round 4
// baseline (speedup 1.0000x reference)
#include <cuda_runtime.h>
#include <cuda_bf16.h>
#include <cstdint>
#include <math.h>

// Problem constants
#define B_      8
#define D_IN_   1024
#define T_      2048
#define CB_SIZE 8192
#define CB_DIM  8
#define NROWS   (B_ * T_)          // 16384
#define EPSV    1e-12f

// Output layout (f32, concatenated in reference return order)
#define OFF_OUT   ((size_t)0)
#define N_OUT     ((size_t)B_ * D_IN_ * T_)             // 16777216
#define OFF_IDX   (N_OUT)                                // 16777216
#define N_IDX     ((size_t)NROWS)                        // 16384
#define OFF_DIST  (OFF_IDX + N_IDX)                      // 16793600
#define N_DIST    ((size_t)NROWS * CB_SIZE)              // 134217728
#define OFF_SCAL  (OFF_DIST + N_DIST)                    // 151011328

// __device__ scratch (no allocations allowed)
__device__ float g_w_in[CB_DIM * D_IN_];    // [c][d]
__device__ float g_w_out[D_IN_ * CB_DIM];   // [d][c]
__device__ float g_cbT[CB_DIM * CB_SIZE];   // [k][j], normalized codebook (transposed)
__device__ float g_cnorm[CB_SIZE];          // sum(cb_n^2) per code
__device__ float g_ze[B_ * CB_DIM * T_];    // [b][c][t]
__device__ float g_counts[CB_SIZE];
__device__ int   g_idx[NROWS];
__device__ float g_loss;

// XLA:CPU / NEON 4-lane vectorized-reduce pattern for 8-element sum of squares:
//   lane acc: a_l = x_l^2 + x_{l+4}^2   (two vector iterations, fadd(fmul))
//   horizontal (shuffle halves): (a0+a2) + (a1+a3)
__device__ __forceinline__ float sum8_sq_xla(const float x[8])
{
    float a0 = __fadd_rn(__fmul_rn(x[0], x[0]), __fmul_rn(x[4], x[4]));
    float a1 = __fadd_rn(__fmul_rn(x[1], x[1]), __fmul_rn(x[5], x[5]));
    float a2 = __fadd_rn(__fmul_rn(x[2], x[2]), __fmul_rn(x[6], x[6]));
    float a3 = __fadd_rn(__fmul_rn(x[3], x[3]), __fmul_rn(x[7], x[7]));
    return __fadd_rn(__fadd_rn(a0, a2), __fadd_rn(a1, a3));
}

// ---------------------------------------------------------------------------
// K1: weight-norm for in/out projections. 1 block x 256.
// v_in row-norm over 1024: XLA/NEON pattern — 4 strided sequential lanes,
// horizontal (a0+a2)+(a1+a3).
// ---------------------------------------------------------------------------
__global__ void k1_prep_w(const float* __restrict__ v_in, const float* __restrict__ g_in,
                          const float* __restrict__ v_out, const float* __restrict__ g_out)
{
    __shared__ float s_norm[CB_DIM];
    int tid = threadIdx.x;

    if (tid < CB_DIM) {
        const float* v = v_in + tid * D_IN_;
        float a[4] = {0.f, 0.f, 0.f, 0.f};
        for (int i = 0; i < D_IN_ / 4; i++) {
            #pragma unroll
            for (int l = 0; l < 4; l++) {
                float x = v[4 * i + l];
                a[l] = __fadd_rn(a[l], __fmul_rn(x, x));
            }
        }
        float h = __fadd_rn(__fadd_rn(a[0], a[2]), __fadd_rn(a[1], a[3]));
        s_norm[tid] = fmaxf(__fsqrt_rn(h), EPSV);
    }
    __syncthreads();

    for (int i = tid; i < CB_DIM * D_IN_; i += 256) {
        int c = i >> 10;
        g_w_in[i] = __fdiv_rn(__fmul_rn(g_in[c], v_in[i]), s_norm[c]);
    }
    // w_out: rows of length 8 (XLA 4-lane 8-sum pattern)
    for (int d = tid; d < D_IN_; d += 256) {
        float v[CB_DIM];
        #pragma unroll
        for (int c = 0; c < CB_DIM; c++) v[c] = v_out[d * CB_DIM + c];
        float nrm = fmaxf(__fsqrt_rn(sum8_sq_xla(v)), EPSV);
        float g = g_out[d];
        #pragma unroll
        for (int c = 0; c < CB_DIM; c++)
            g_w_out[d * CB_DIM + c] = __fdiv_rn(__fmul_rn(g, v[c]), nrm);
    }
    if (tid == 0) g_loss = 0.f;
}

// ---------------------------------------------------------------------------
// K2: normalize codebook -> transposed layout; zero counts. grid 32 x 256.
// ---------------------------------------------------------------------------
__global__ void k2_prep_cb(const float* __restrict__ codebook)
{
    int j = blockIdx.x * 256 + threadIdx.x;
    float v[CB_DIM];
    #pragma unroll
    for (int c = 0; c < CB_DIM; c++) v[c] = codebook[(size_t)j * CB_DIM + c];
    float nrm = fmaxf(__fsqrt_rn(sum8_sq_xla(v)), EPSV);
    float x[CB_DIM];
    #pragma unroll
    for (int c = 0; c < CB_DIM; c++) {
        x[c] = __fdiv_rn(v[c], nrm);
        g_cbT[c * CB_SIZE + j] = x[c];
    }
    g_cnorm[j] = sum8_sq_xla(x);
    g_counts[j] = 0.f;
}

// ---------------------------------------------------------------------------
// K3: z_e[b][c][t] = b_in[c] + sum_d w_in[c][d] * z[b][d][t]
// STRICT sequential fma over d=0..1023 (Eigen gebp ascending-k).
// 128 blocks x 128 threads (one thread per row).
// ---------------------------------------------------------------------------
__global__ void k3_ze(const float* __restrict__ z, const float* __restrict__ b_in)
{
    __shared__ float s_w[D_IN_ * CB_DIM];   // [d][c], 32 KB
    int tid = threadIdx.x;
    for (int i = tid; i < D_IN_ * CB_DIM; i += 128) {
        int d = i >> 3, c = i & 7;
        s_w[i] = g_w_in[c * D_IN_ + d];
    }
    __syncthreads();

    int row = blockIdx.x * 128 + tid;          // 16384 rows
    int b = row >> 11, t = row & (T_ - 1);
    const float* zp = z + (size_t)b * D_IN_ * T_ + t;

    float acc[CB_DIM] = {0.f, 0.f, 0.f, 0.f, 0.f, 0.f, 0.f, 0.f};

    for (int d0 = 0; d0 < D_IN_; d0 += 16) {
        float v[16];
        #pragma unroll
        for (int u = 0; u < 16; u++) v[u] = zp[(size_t)(d0 + u) * T_];
        #pragma unroll
        for (int u = 0; u < 16; u++) {
            float4 w0 = *(const float4*)&s_w[(d0 + u) * 8];
            float4 w1 = *(const float4*)&s_w[(d0 + u) * 8 + 4];
            acc[0] = __fmaf_rn(w0.x, v[u], acc[0]);
            acc[1] = __fmaf_rn(w0.y, v[u], acc[1]);
            acc[2] = __fmaf_rn(w0.z, v[u], acc[2]);
            acc[3] = __fmaf_rn(w0.w, v[u], acc[3]);
            acc[4] = __fmaf_rn(w1.x, v[u], acc[4]);
            acc[5] = __fmaf_rn(w1.y, v[u], acc[5]);
            acc[6] = __fmaf_rn(w1.z, v[u], acc[6]);
            acc[7] = __fmaf_rn(w1.w, v[u], acc[7]);
        }
    }
    #pragma unroll
    for (int c = 0; c < CB_DIM; c++)
        g_ze[((size_t)b * CB_DIM + c) * T_ + t] = __fadd_rn(acc[c], b_in[c]);
}

// ---------------------------------------------------------------------------
// K4: dist matrix (full write) + argmin. 512 blocks x 256 threads.
// dist = (en - 2*dot) + cn; dot = ascending-k fma chain (Eigen). Argmin =
// first occurrence. enc norm + en use the XLA 4-lane 8-sum pattern.
// ---------------------------------------------------------------------------
#define K4_ROWS 32
#define K4_CHUNK 1024

__global__ void k4_dist(float* __restrict__ dist_out, float* __restrict__ idxf_out)
{
    __shared__ float s_cbT[CB_DIM][K4_CHUNK];
    __shared__ float s_cn[K4_CHUNK];
    __shared__ float s_e[K4_ROWS][CB_DIM];
    __shared__ float s_en[K4_ROWS];

    int tid = threadIdx.x;
    int row0 = blockIdx.x * K4_ROWS;

    // stage this block's encoder rows
    {
        int r = tid >> 3, c = tid & 7;
        int row = row0 + r;
        int b = row >> 11, t = row & (T_ - 1);
        s_e[r][c] = g_ze[((size_t)b * CB_DIM + c) * T_ + t];
    }
    __syncthreads();
    // normalize (XLA 4-lane 8-sum, IEEE division)
    if (tid < K4_ROWS) {
        float v[CB_DIM];
        #pragma unroll
        for (int c = 0; c < CB_DIM; c++) v[c] = s_e[tid][c];
        float nrm = fmaxf(__fsqrt_rn(sum8_sq_xla(v)), EPSV);
        float x[CB_DIM];
        #pragma unroll
        for (int c = 0; c < CB_DIM; c++) {
            x[c] = __fdiv_rn(v[c], nrm);
            s_e[tid][c] = x[c];
        }
        s_en[tid] = sum8_sq_xla(x);
    }
    __syncthreads();

    int warp = tid >> 5, lane = tid & 31;
    float e[4][CB_DIM], en[4];
    #pragma unroll
    for (int r = 0; r < 4; r++) {
        en[r] = s_en[warp * 4 + r];
        #pragma unroll
        for (int k = 0; k < CB_DIM; k++) e[r][k] = s_e[warp * 4 + r][k];
    }

    float minv[4] = {3.4e38f, 3.4e38f, 3.4e38f, 3.4e38f};
    int   mini[4] = {0, 0, 0, 0};

    for (int ch = 0; ch < CB_SIZE / K4_CHUNK; ch++) {
        __syncthreads();
        for (int i = tid; i < CB_DIM * (K4_CHUNK / 4); i += 256) {
            int k = i / (K4_CHUNK / 4);
            int j4 = i % (K4_CHUNK / 4);
            ((float4*)s_cbT[k])[j4] =
                ((const float4*)(g_cbT + k * CB_SIZE + ch * K4_CHUNK))[j4];
        }
        for (int i = tid; i < K4_CHUNK / 4; i += 256)
            ((float4*)s_cn)[i] = ((const float4*)(g_cnorm + ch * K4_CHUNK))[i];
        __syncthreads();

        #pragma unroll
        for (int it = 0; it < K4_CHUNK / 128; it++) {
            int cbase = it * 128 + lane * 4;
            float4 c4[CB_DIM];
            #pragma unroll
            for (int k = 0; k < CB_DIM; k++) c4[k] = *(const float4*)&s_cbT[k][cbase];
            float4 cn4 = *(const float4*)&s_cn[cbase];
            int gcol = ch * K4_CHUNK + cbase;

            #pragma unroll
            for (int r = 0; r < 4; r++) {
                float tx = 0.f, ty = 0.f, tz = 0.f, tw = 0.f;
                #pragma unroll
                for (int k = 0; k < CB_DIM; k++) {
                    tx = __fmaf_rn(e[r][k], c4[k].x, tx);
                    ty = __fmaf_rn(e[r][k], c4[k].y, ty);
                    tz = __fmaf_rn(e[r][k], c4[k].z, tz);
                    tw = __fmaf_rn(e[r][k], c4[k].w, tw);
                }
                // dist = (en - 2*dot) + cn  (reference association; 2*dot exact)
                float4 d4;
                d4.x = __fadd_rn(__fadd_rn(en[r], -(2.f * tx)), cn4.x);
                d4.y = __fadd_rn(__fadd_rn(en[r], -(2.f * ty)), cn4.y);
                d4.z = __fadd_rn(__fadd_rn(en[r], -(2.f * tz)), cn4.z);
                d4.w = __fadd_rn(__fadd_rn(en[r], -(2.f * tw)), cn4.w);

                int row = row0 + warp * 4 + r;
                *(float4*)&dist_out[(size_t)row * CB_SIZE + gcol] = d4;

                if (d4.x < minv[r]) { minv[r] = d4.x; mini[r] = gcol; }
                if (d4.y < minv[r]) { minv[r] = d4.y; mini[r] = gcol + 1; }
                if (d4.z < minv[r]) { minv[r] = d4.z; mini[r] = gcol + 2; }
                if (d4.w < minv[r]) { minv[r] = d4.w; mini[r] = gcol + 3; }
            }
        }
    }

    // per-row warp reduction, tie-break to lowest index (first occurrence)
    #pragma unroll
    for (int r = 0; r < 4; r++) {
        float v = minv[r]; int i = mini[r];
        #pragma unroll
        for (int off = 16; off; off >>= 1) {
            float ov = __shfl_down_sync(0xffffffffu, v, off);
            int   oi = __shfl_down_sync(0xffffffffu, i, off);
            if (ov < v || (ov == v && oi < i)) { v = ov; i = oi; }
        }
        if (lane == 0) {
            int row = row0 + warp * 4 + r;
            g_idx[row] = i;
            idxf_out[row] = (float)i;
        }
    }
}

// ---------------------------------------------------------------------------
// K5: histogram + commitment-loss accumulation. grid 64 x 256.
// ---------------------------------------------------------------------------
__global__ void k5_post(const float* __restrict__ codebook)
{
    int row = blockIdx.x * 256 + threadIdx.x;
    int b = row >> 11, t = row & (T_ - 1);
    int idx = g_idx[row];
    atomicAdd(&g_counts[idx], 1.f);

    float s = 0.f;
    #pragma unroll
    for (int c = 0; c < CB_DIM; c++) {
        float d = g_ze[((size_t)b * CB_DIM + c) * T_ + t] - codebook[(size_t)idx * CB_DIM + c];
        s = fmaf(d, d, s);
    }
    #pragma unroll
    for (int off = 16; off; off >>= 1) s += __shfl_down_sync(0xffffffffu, s, off);
    if ((threadIdx.x & 31) == 0) atomicAdd(&g_loss, s);
}

// ---------------------------------------------------------------------------
// K6: out[b][d][t] = b_out[d] + sum_c w_out[d][c] * z_q_st[b][c][t]
// z_q_st = z_e + (z_q - z_e) in fp32. grid (8 tchunks, 8 b, 8 dchunks), 256.
// ---------------------------------------------------------------------------
__global__ void k6_out(const float* __restrict__ codebook, const float* __restrict__ b_out,
                       float* __restrict__ out)
{
    __shared__ float s_w[128][CB_DIM];
    __shared__ float s_b[128];
    int tid = threadIdx.x;
    int tch = blockIdx.x, b = blockIdx.y, dch = blockIdx.z;

    for (int i = tid; i < 128 * CB_DIM; i += 256) {
        int dd = i >> 3, c = i & 7;
        s_w[dd][c] = g_w_out[(dch * 128 + dd) * CB_DIM + c];
    }
    if (tid < 128) s_b[tid] = b_out[dch * 128 + tid];
    __syncthreads();

    int t = tch * 256 + tid;
    int idx = g_idx[b * T_ + t];
    float q[CB_DIM];
    const float* cb = codebook + (size_t)idx * CB_DIM;
    #pragma unroll
    for (int c = 0; c < CB_DIM; c++) {
        float ze = g_ze[((size_t)b * CB_DIM + c) * T_ + t];
        float zq = cb[c];
        q[c] = __fadd_rn(ze, __fadd_rn(zq, -ze));   // straight-through z_q_st
    }

    float* op = out + ((size_t)b * D_IN_ + dch * 128) * T_ + t;
    #pragma unroll 4
    for (int dd = 0; dd < 128; dd++) {
        float a = 0.f;
        #pragma unroll
        for (int c = 0; c < CB_DIM; c++) a = __fmaf_rn(s_w[dd][c], q[c], a);
        op[(size_t)dd * T_] = __fadd_rn(a, s_b[dd]);
    }
}

// ---------------------------------------------------------------------------
// K7: scalars (vq_loss, perplexity, active_num). 1 block x 256.
// ---------------------------------------------------------------------------
__global__ void k7_final(float* __restrict__ scal)
{
    __shared__ float s_s[256];
    __shared__ float s_a[256];
    int tid = threadIdx.x;
    float s = 0.f, a = 0.f;
    for (int i = tid; i < CB_SIZE; i += 256) {
        float c = g_counts[i];
        float p = c / (float)NROWS;
        s += p * logf(p + 1e-10f);
        if (c * (1.0f - 0.99f) > 2.0f) a += 1.f;
    }
    s_s[tid] = s; s_a[tid] = a;
    __syncthreads();
    for (int off = 128; off; off >>= 1) {
        if (tid < off) { s_s[tid] += s_s[tid + off]; s_a[tid] += s_a[tid + off]; }
        __syncthreads();
    }
    if (tid == 0) {
        scal[0] = g_loss * 1.25f / (float)(B_ * CB_DIM * T_);  // vq_loss
        scal[1] = expf(-s_s[0]);                               // perplexity
        scal[2] = s_a[0];                                      // active_num
    }
}

// ---------------------------------------------------------------------------
extern "C" void kernel_launch(void* const* d_in, const int* in_sizes, int n_in,
                              void* d_out, int out_size)
{
    const float* z        = (const float*)d_in[0];
    const float* codebook = (const float*)d_in[1];
    const float* v_in     = (const float*)d_in[2];
    const float* g_in     = (const float*)d_in[3];
    const float* b_in     = (const float*)d_in[4];
    const float* v_out    = (const float*)d_in[5];
    const float* g_out    = (const float*)d_in[6];
    const float* b_out    = (const float*)d_in[7];
    float* out = (float*)d_out;

    k1_prep_w<<<1, 256>>>(v_in, g_in, v_out, g_out);
    k2_prep_cb<<<32, 256>>>(codebook);
    k3_ze<<<128, 128>>>(z, b_in);
    k4_dist<<<NROWS / K4_ROWS, 256>>>(out + OFF_DIST, out + OFF_IDX);
    k5_post<<<64, 256>>>(codebook);
    k6_out<<<dim3(8, 8, 8), 256>>>(codebook, b_out, out + OFF_OUT);
    k7_final<<<1, 256>>>(out + OFF_SCAL);
}

// round 5
// speedup vs baseline: 1.3134x; 1.3134x over previous
#include <cuda_runtime.h>
#include <cuda_bf16.h>
#include <cstdint>
#include <math.h>

// Problem constants
#define B_      8
#define D_IN_   1024
#define T_      2048
#define CB_SIZE 8192
#define CB_DIM  8
#define NROWS   (B_ * T_)          // 16384
#define EPSV    1e-12f

// Output layout (f32, concatenated in reference return order)
#define OFF_OUT   ((size_t)0)
#define N_OUT     ((size_t)B_ * D_IN_ * T_)             // 16777216
#define OFF_IDX   (N_OUT)                                // 16777216
#define N_IDX     ((size_t)NROWS)                        // 16384
#define OFF_DIST  (OFF_IDX + N_IDX)                      // 16793600
#define N_DIST    ((size_t)NROWS * CB_SIZE)              // 134217728
#define OFF_SCAL  (OFF_DIST + N_DIST)                    // 151011328

// __device__ scratch (no allocations allowed)
__device__ float g_w_in[CB_DIM * D_IN_];    // [c][d]
__device__ float g_w_out[D_IN_ * CB_DIM];   // [d][c]
__device__ float g_cbT[CB_DIM * CB_SIZE];   // [k][j], normalized codebook (transposed)
__device__ float g_cnorm[CB_SIZE];          // sum(cb_n^2) per code
__device__ float g_ze[B_ * CB_DIM * T_];    // [b][c][t]
__device__ float g_counts[CB_SIZE];
__device__ int   g_idx[NROWS];
__device__ float g_loss;

// XLA:CPU / NEON 4-lane vectorized-reduce pattern for 8-element sum of squares:
//   lane acc: a_l = x_l^2 + x_{l+4}^2, horizontal (a0+a2) + (a1+a3)
__device__ __forceinline__ float sum8_sq_xla(const float x[8])
{
    float a0 = __fadd_rn(__fmul_rn(x[0], x[0]), __fmul_rn(x[4], x[4]));
    float a1 = __fadd_rn(__fmul_rn(x[1], x[1]), __fmul_rn(x[5], x[5]));
    float a2 = __fadd_rn(__fmul_rn(x[2], x[2]), __fmul_rn(x[6], x[6]));
    float a3 = __fadd_rn(__fmul_rn(x[3], x[3]), __fmul_rn(x[7], x[7]));
    return __fadd_rn(__fadd_rn(a0, a2), __fadd_rn(a1, a3));
}

// ---------------------------------------------------------------------------
// K1: weight-norm for in/out projections. 1 block x 256. (arithmetic frozen)
// ---------------------------------------------------------------------------
__global__ void k1_prep_w(const float* __restrict__ v_in, const float* __restrict__ g_in,
                          const float* __restrict__ v_out, const float* __restrict__ g_out)
{
    __shared__ float s_norm[CB_DIM];
    int tid = threadIdx.x;

    if (tid < CB_DIM) {
        const float* v = v_in + tid * D_IN_;
        float a[4] = {0.f, 0.f, 0.f, 0.f};
        for (int i = 0; i < D_IN_ / 4; i++) {
            #pragma unroll
            for (int l = 0; l < 4; l++) {
                float x = v[4 * i + l];
                a[l] = __fadd_rn(a[l], __fmul_rn(x, x));
            }
        }
        float h = __fadd_rn(__fadd_rn(a[0], a[2]), __fadd_rn(a[1], a[3]));
        s_norm[tid] = fmaxf(__fsqrt_rn(h), EPSV);
    }
    __syncthreads();

    for (int i = tid; i < CB_DIM * D_IN_; i += 256) {
        int c = i >> 10;
        g_w_in[i] = __fdiv_rn(__fmul_rn(g_in[c], v_in[i]), s_norm[c]);
    }
    for (int d = tid; d < D_IN_; d += 256) {
        float v[CB_DIM];
        #pragma unroll
        for (int c = 0; c < CB_DIM; c++) v[c] = v_out[d * CB_DIM + c];
        float nrm = fmaxf(__fsqrt_rn(sum8_sq_xla(v)), EPSV);
        float g = g_out[d];
        #pragma unroll
        for (int c = 0; c < CB_DIM; c++)
            g_w_out[d * CB_DIM + c] = __fdiv_rn(__fmul_rn(g, v[c]), nrm);
    }
    if (tid == 0) g_loss = 0.f;
}

// ---------------------------------------------------------------------------
// K2: normalize codebook -> transposed layout; zero counts. grid 32 x 256.
// ---------------------------------------------------------------------------
__global__ void k2_prep_cb(const float* __restrict__ codebook)
{
    int j = blockIdx.x * 256 + threadIdx.x;
    float v[CB_DIM];
    #pragma unroll
    for (int c = 0; c < CB_DIM; c++) v[c] = codebook[(size_t)j * CB_DIM + c];
    float nrm = fmaxf(__fsqrt_rn(sum8_sq_xla(v)), EPSV);
    float x[CB_DIM];
    #pragma unroll
    for (int c = 0; c < CB_DIM; c++) {
        x[c] = __fdiv_rn(v[c], nrm);
        g_cbT[c * CB_SIZE + j] = x[c];
    }
    g_cnorm[j] = sum8_sq_xla(x);
    g_counts[j] = 0.f;
}

// ---------------------------------------------------------------------------
// K3: z_e — strict sequential fma over d (arithmetic frozen). 128 x 128.
// ---------------------------------------------------------------------------
__global__ void k3_ze(const float* __restrict__ z, const float* __restrict__ b_in)
{
    __shared__ float s_w[D_IN_ * CB_DIM];   // [d][c], 32 KB
    int tid = threadIdx.x;
    for (int i = tid; i < D_IN_ * CB_DIM; i += 128) {
        int d = i >> 3, c = i & 7;
        s_w[i] = g_w_in[c * D_IN_ + d];
    }
    __syncthreads();

    int row = blockIdx.x * 128 + tid;          // 16384 rows
    int b = row >> 11, t = row & (T_ - 1);
    const float* zp = z + (size_t)b * D_IN_ * T_ + t;

    float acc[CB_DIM] = {0.f, 0.f, 0.f, 0.f, 0.f, 0.f, 0.f, 0.f};

    for (int d0 = 0; d0 < D_IN_; d0 += 16) {
        float v[16];
        #pragma unroll
        for (int u = 0; u < 16; u++) v[u] = zp[(size_t)(d0 + u) * T_];
        #pragma unroll
        for (int u = 0; u < 16; u++) {
            float4 w0 = *(const float4*)&s_w[(d0 + u) * 8];
            float4 w1 = *(const float4*)&s_w[(d0 + u) * 8 + 4];
            acc[0] = __fmaf_rn(w0.x, v[u], acc[0]);
            acc[1] = __fmaf_rn(w0.y, v[u], acc[1]);
            acc[2] = __fmaf_rn(w0.z, v[u], acc[2]);
            acc[3] = __fmaf_rn(w0.w, v[u], acc[3]);
            acc[4] = __fmaf_rn(w1.x, v[u], acc[4]);
            acc[5] = __fmaf_rn(w1.y, v[u], acc[5]);
            acc[6] = __fmaf_rn(w1.z, v[u], acc[6]);
            acc[7] = __fmaf_rn(w1.w, v[u], acc[7]);
        }
    }
    #pragma unroll
    for (int c = 0; c < CB_DIM; c++)
        g_ze[((size_t)b * CB_DIM + c) * T_ + t] = __fadd_rn(acc[c], b_in[c]);
}

// ---------------------------------------------------------------------------
// K4: dist (streamed store) + argmin + fused counts/loss.
// 1024 blocks x 128 threads; 16 rows/block, 4 rows/warp, 4 cols/lane.
// dist arithmetic bit-identical to R4. Argmin: fmin-tree + rare branch
// recovering first-occurrence index.
// ---------------------------------------------------------------------------
#define K4_ROWS 16
#define K4_CHUNK 1024

__global__ void __launch_bounds__(128)
k4_dist(const float* __restrict__ codebook,
        float* __restrict__ dist_out, float* __restrict__ idxf_out)
{
    __shared__ float s_cbT[CB_DIM][K4_CHUNK];
    __shared__ float s_cn[K4_CHUNK];
    __shared__ float s_raw[K4_ROWS][CB_DIM];
    __shared__ float s_e[K4_ROWS][CB_DIM];
    __shared__ float s_en[K4_ROWS];
    __shared__ int   s_idx[K4_ROWS];

    int tid = threadIdx.x;
    int row0 = blockIdx.x * K4_ROWS;

    // stage raw encoder rows (128 threads cover 16x8 exactly)
    {
        int r = tid >> 3, c = tid & 7;
        int row = row0 + r;
        int b = row >> 11, t = row & (T_ - 1);
        s_raw[r][c] = g_ze[((size_t)b * CB_DIM + c) * T_ + t];
    }
    __syncthreads();
    // normalize (XLA 4-lane 8-sum, IEEE division) — frozen arithmetic
    if (tid < K4_ROWS) {
        float v[CB_DIM];
        #pragma unroll
        for (int c = 0; c < CB_DIM; c++) v[c] = s_raw[tid][c];
        float nrm = fmaxf(__fsqrt_rn(sum8_sq_xla(v)), EPSV);
        float x[CB_DIM];
        #pragma unroll
        for (int c = 0; c < CB_DIM; c++) {
            x[c] = __fdiv_rn(v[c], nrm);
            s_e[tid][c] = x[c];
        }
        s_en[tid] = sum8_sq_xla(x);
    }
    __syncthreads();

    int warp = tid >> 5, lane = tid & 31;
    float e[4][CB_DIM], en[4];
    float* dp[4];
    #pragma unroll
    for (int r = 0; r < 4; r++) {
        int rr = warp * 4 + r;
        en[r] = s_en[rr];
        #pragma unroll
        for (int k = 0; k < CB_DIM; k++) e[r][k] = s_e[rr][k];
        dp[r] = dist_out + (size_t)(row0 + rr) * CB_SIZE;
    }

    float minv[4] = {3.4e38f, 3.4e38f, 3.4e38f, 3.4e38f};
    int   mini[4] = {0, 0, 0, 0};

    for (int ch = 0; ch < CB_SIZE / K4_CHUNK; ch++) {
        __syncthreads();
        for (int i = tid; i < CB_DIM * (K4_CHUNK / 4); i += 128) {
            int k = i / (K4_CHUNK / 4);
            int j4 = i % (K4_CHUNK / 4);
            ((float4*)s_cbT[k])[j4] =
                ((const float4*)(g_cbT + k * CB_SIZE + ch * K4_CHUNK))[j4];
        }
        for (int i = tid; i < K4_CHUNK / 4; i += 128)
            ((float4*)s_cn)[i] = ((const float4*)(g_cnorm + ch * K4_CHUNK))[i];
        __syncthreads();

        #pragma unroll
        for (int it = 0; it < K4_CHUNK / 128; it++) {
            int cbase = it * 128 + lane * 4;
            float4 c4[CB_DIM];
            #pragma unroll
            for (int k = 0; k < CB_DIM; k++) c4[k] = *(const float4*)&s_cbT[k][cbase];
            float4 cn4 = *(const float4*)&s_cn[cbase];
            int gcol = ch * K4_CHUNK + cbase;

            #pragma unroll
            for (int r = 0; r < 4; r++) {
                float tx = 0.f, ty = 0.f, tz = 0.f, tw = 0.f;
                #pragma unroll
                for (int k = 0; k < CB_DIM; k++) {
                    tx = __fmaf_rn(e[r][k], c4[k].x, tx);
                    ty = __fmaf_rn(e[r][k], c4[k].y, ty);
                    tz = __fmaf_rn(e[r][k], c4[k].z, tz);
                    tw = __fmaf_rn(e[r][k], c4[k].w, tw);
                }
                // dist = (en - 2*dot) + cn  (bit-identical to passing version)
                float4 d4;
                d4.x = __fadd_rn(__fadd_rn(en[r], -(2.f * tx)), cn4.x);
                d4.y = __fadd_rn(__fadd_rn(en[r], -(2.f * ty)), cn4.y);
                d4.z = __fadd_rn(__fadd_rn(en[r], -(2.f * tz)), cn4.z);
                d4.w = __fadd_rn(__fadd_rn(en[r], -(2.f * tw)), cn4.w);

                __stcs((float4*)(dp[r] + gcol), d4);

                // fmin tree + rare branch for first-occurrence index
                float m = fminf(fminf(d4.x, d4.y), fminf(d4.z, d4.w));
                if (m < minv[r]) {
                    minv[r] = m;
                    int off = (d4.x == m) ? 0 : (d4.y == m) ? 1 : (d4.z == m) ? 2 : 3;
                    mini[r] = gcol + off;
                }
            }
        }
    }

    // per-row warp reduction, tie-break to lowest index (first occurrence)
    #pragma unroll
    for (int r = 0; r < 4; r++) {
        float v = minv[r]; int i = mini[r];
        #pragma unroll
        for (int off = 16; off; off >>= 1) {
            float ov = __shfl_down_sync(0xffffffffu, v, off);
            int   oi = __shfl_down_sync(0xffffffffu, i, off);
            if (ov < v || (ov == v && oi < i)) { v = ov; i = oi; }
        }
        if (lane == 0) {
            int rr = warp * 4 + r;
            g_idx[row0 + rr] = i;
            idxf_out[row0 + rr] = (float)i;
            s_idx[rr] = i;
        }
    }
    __syncthreads();

    // fused counts histogram + commitment loss (per row, then block-reduce)
    if (tid < K4_ROWS) {
        int idx = s_idx[tid];
        atomicAdd(&g_counts[idx], 1.f);
        const float* cb = codebook + (size_t)idx * CB_DIM;
        float s = 0.f;
        #pragma unroll
        for (int c = 0; c < CB_DIM; c++) {
            float d = s_raw[tid][c] - cb[c];
            s = fmaf(d, d, s);
        }
        s += __shfl_down_sync(0x0000ffffu, s, 8);
        s += __shfl_down_sync(0x0000ffffu, s, 4);
        s += __shfl_down_sync(0x0000ffffu, s, 2);
        s += __shfl_down_sync(0x0000ffffu, s, 1);
        if (tid == 0) atomicAdd(&g_loss, s);
    }
}

// ---------------------------------------------------------------------------
// K6: out[b][d][t] = b_out[d] + sum_c w_out[d][c] * z_q_st[b][c][t]
// float4 over t: each thread handles 4 consecutive t. grid (4, 8, 8) x 128.
// ---------------------------------------------------------------------------
__global__ void __launch_bounds__(128)
k6_out(const float* __restrict__ codebook, const float* __restrict__ b_out,
       float* __restrict__ out)
{
    __shared__ float s_w[128][CB_DIM];
    __shared__ float s_b[128];
    int tid = threadIdx.x;
    int tch = blockIdx.x, b = blockIdx.y, dch = blockIdx.z;

    for (int i = tid; i < 128 * CB_DIM; i += 128) {
        int dd = i >> 3, c = i & 7;
        s_w[dd][c] = g_w_out[(dch * 128 + dd) * CB_DIM + c];
    }
    s_b[tid] = b_out[dch * 128 + tid];
    __syncthreads();

    int t0 = tch * 512 + tid * 4;   // 4 consecutive t per thread
    float q[4][CB_DIM];
    #pragma unroll
    for (int j = 0; j < 4; j++) {
        int idx = g_idx[b * T_ + t0 + j];
        const float* cb = codebook + (size_t)idx * CB_DIM;
        #pragma unroll
        for (int c = 0; c < CB_DIM; c++) {
            float ze = g_ze[((size_t)b * CB_DIM + c) * T_ + t0 + j];
            float zq = cb[c];
            q[j][c] = __fadd_rn(ze, __fadd_rn(zq, -ze));   // straight-through
        }
    }

    float* op = out + ((size_t)b * D_IN_ + dch * 128) * T_ + t0;
    #pragma unroll 4
    for (int dd = 0; dd < 128; dd++) {
        float4 o;
        float bb = s_b[dd];
        const float* w = s_w[dd];
        float a0 = 0.f, a1 = 0.f, a2 = 0.f, a3 = 0.f;
        #pragma unroll
        for (int c = 0; c < CB_DIM; c++) {
            float wc = w[c];
            a0 = __fmaf_rn(wc, q[0][c], a0);
            a1 = __fmaf_rn(wc, q[1][c], a1);
            a2 = __fmaf_rn(wc, q[2][c], a2);
            a3 = __fmaf_rn(wc, q[3][c], a3);
        }
        o.x = __fadd_rn(a0, bb);
        o.y = __fadd_rn(a1, bb);
        o.z = __fadd_rn(a2, bb);
        o.w = __fadd_rn(a3, bb);
        *(float4*)(op + (size_t)dd * T_) = o;
    }
}

// ---------------------------------------------------------------------------
// K7: scalars (vq_loss, perplexity, active_num). 1 block x 256.
// ---------------------------------------------------------------------------
__global__ void k7_final(float* __restrict__ scal)
{
    __shared__ float s_s[256];
    __shared__ float s_a[256];
    int tid = threadIdx.x;
    float s = 0.f, a = 0.f;
    for (int i = tid; i < CB_SIZE; i += 256) {
        float c = g_counts[i];
        float p = c / (float)NROWS;
        s += p * logf(p + 1e-10f);
        if (c * (1.0f - 0.99f) > 2.0f) a += 1.f;
    }
    s_s[tid] = s; s_a[tid] = a;
    __syncthreads();
    for (int off = 128; off; off >>= 1) {
        if (tid < off) { s_s[tid] += s_s[tid + off]; s_a[tid] += s_a[tid + off]; }
        __syncthreads();
    }
    if (tid == 0) {
        scal[0] = g_loss * 1.25f / (float)(B_ * CB_DIM * T_);  // vq_loss
        scal[1] = expf(-s_s[0]);                               // perplexity
        scal[2] = s_a[0];                                      // active_num
    }
}

// ---------------------------------------------------------------------------
extern "C" void kernel_launch(void* const* d_in, const int* in_sizes, int n_in,
                              void* d_out, int out_size)
{
    const float* z        = (const float*)d_in[0];
    const float* codebook = (const float*)d_in[1];
    const float* v_in     = (const float*)d_in[2];
    const float* g_in     = (const float*)d_in[3];
    const float* b_in     = (const float*)d_in[4];
    const float* v_out    = (const float*)d_in[5];
    const float* g_out    = (const float*)d_in[6];
    const float* b_out    = (const float*)d_in[7];
    float* out = (float*)d_out;

    k1_prep_w<<<1, 256>>>(v_in, g_in, v_out, g_out);
    k2_prep_cb<<<32, 256>>>(codebook);
    k3_ze<<<128, 128>>>(z, b_in);
    k4_dist<<<NROWS / K4_ROWS, 128>>>(codebook, out + OFF_DIST, out + OFF_IDX);
    k6_out<<<dim3(4, 8, 8), 128>>>(codebook, b_out, out + OFF_OUT);
    k7_final<<<1, 256>>>(out + OFF_SCAL);
}